// round 3
// baseline (speedup 1.0000x reference)
#include <cuda_runtime.h>
#include <cuda_bf16.h>

// Problem: B=1, N=4096, H=16, D=64, C=1024
static constexpr int SEQ   = 4096;
static constexpr int CDIM  = 1024;
static constexpr int QKV3  = 3 * CDIM;   // 3072
static constexpr float SCALE = 0.125f;   // 64^-0.5

// Scratch (no allocs allowed): qkv [N, 3C] and attention output [N, C]
__device__ float g_qkv[SEQ * QKV3];
__device__ float g_attn[SEQ * CDIM];

// ---------------------------------------------------------------------------
// C[m,n] = sum_k A[m,k] * B[n,k] (+ bias[n])   (both A,B row-major, K contiguous)
// 128x128 block tile, K-tile 16, 256 threads, 8x8 per thread.
// ---------------------------------------------------------------------------
template <bool BIAS>
__global__ __launch_bounds__(256) void gemm_nt_kernel(
    const float* __restrict__ A, const float* __restrict__ B,
    const float* __restrict__ bias, float* __restrict__ C,
    int M, int N, int K)
{
    __shared__ float As[16][128];
    __shared__ float Bs[16][128];

    const int bm = blockIdx.y * 128;
    const int bn = blockIdx.x * 128;
    const int tid = threadIdx.x;
    const int tx = tid & 15;   // column group (8 cols)
    const int ty = tid >> 4;   // row group (8 rows)

    float acc[8][8];
#pragma unroll
    for (int i = 0; i < 8; i++)
#pragma unroll
        for (int j = 0; j < 8; j++) acc[i][j] = 0.f;

    for (int k0 = 0; k0 < K; k0 += 16) {
#pragma unroll
        for (int it = 0; it < 2; it++) {
            int slot = tid + it * 256;       // 0..511 float4 slots
            int row  = slot >> 2;            // 0..127
            int kc   = (slot & 3) * 4;       // 0,4,8,12
            float4 a = *reinterpret_cast<const float4*>(
                &A[(size_t)(bm + row) * K + k0 + kc]);
            As[kc + 0][row] = a.x; As[kc + 1][row] = a.y;
            As[kc + 2][row] = a.z; As[kc + 3][row] = a.w;
            float4 b = *reinterpret_cast<const float4*>(
                &B[(size_t)(bn + row) * K + k0 + kc]);
            Bs[kc + 0][row] = b.x; Bs[kc + 1][row] = b.y;
            Bs[kc + 2][row] = b.z; Bs[kc + 3][row] = b.w;
        }
        __syncthreads();

#pragma unroll
        for (int kk = 0; kk < 16; kk++) {
            float ar[8], br[8];
            *reinterpret_cast<float4*>(&ar[0]) =
                *reinterpret_cast<const float4*>(&As[kk][ty * 8]);
            *reinterpret_cast<float4*>(&ar[4]) =
                *reinterpret_cast<const float4*>(&As[kk][ty * 8 + 4]);
            *reinterpret_cast<float4*>(&br[0]) =
                *reinterpret_cast<const float4*>(&Bs[kk][tx * 8]);
            *reinterpret_cast<float4*>(&br[4]) =
                *reinterpret_cast<const float4*>(&Bs[kk][tx * 8 + 4]);
#pragma unroll
            for (int i = 0; i < 8; i++)
#pragma unroll
                for (int j = 0; j < 8; j++)
                    acc[i][j] = fmaf(ar[i], br[j], acc[i][j]);
        }
        __syncthreads();
    }

#pragma unroll
    for (int i = 0; i < 8; i++) {
        const int row = bm + ty * 8 + i;
#pragma unroll
        for (int j4 = 0; j4 < 2; j4++) {
            const int col = bn + tx * 8 + j4 * 4;
            float4 v;
            v.x = acc[i][j4 * 4 + 0]; v.y = acc[i][j4 * 4 + 1];
            v.z = acc[i][j4 * 4 + 2]; v.w = acc[i][j4 * 4 + 3];
            if (BIAS) {
                v.x += bias[col + 0]; v.y += bias[col + 1];
                v.z += bias[col + 2]; v.w += bias[col + 3];
            }
            *reinterpret_cast<float4*>(&C[(size_t)row * N + col]) = v;
        }
    }
}

// ---------------------------------------------------------------------------
// Flash attention (causal), fp32. One block = 64 query rows x one head.
// 256 threads as 16x16; each thread owns a 4x4 fragment. Online softmax state
// (m, l) lives replicated in the 16 lanes that own each row (shuffle reduce).
// ---------------------------------------------------------------------------
__global__ __launch_bounds__(256) void attn_kernel(const float* __restrict__ qkv,
                                                   float* __restrict__ out)
{
    extern __shared__ float sm[];
    float* Qt = sm;              // [d][r]  64*64
    float* Kt = sm + 4096;       // [d][c]  64*64
    float* Vs = sm + 8192;       // [s][d]  64*64
    float* Pt = sm + 12288;      // [s][r]  64*65 (padded)

    const int qi = gridDim.x - 1 - blockIdx.x;   // reverse for causal balance
    const int h  = blockIdx.y;
    const int tid = threadIdx.x;
    const int tx = tid & 15;
    const int ty = tid >> 4;
    const int qbase = qi * 64;

    // Load Q tile transposed: Qt[d][r]
    const float* qptr = qkv + (size_t)qbase * QKV3 + h * 64;
#pragma unroll
    for (int it = 0; it < 4; it++) {
        int slot = tid + it * 256;       // 0..1023 float4 slots
        int r  = slot >> 4;              // 0..63
        int d4 = (slot & 15) * 4;        // 0..60
        float4 v = *reinterpret_cast<const float4*>(&qptr[(size_t)r * QKV3 + d4]);
        Qt[(d4 + 0) * 64 + r] = v.x;
        Qt[(d4 + 1) * 64 + r] = v.y;
        Qt[(d4 + 2) * 64 + r] = v.z;
        Qt[(d4 + 3) * 64 + r] = v.w;
    }

    float o[4][4];
    float m_i[4], l_i[4];
#pragma unroll
    for (int i = 0; i < 4; i++) {
        m_i[i] = -1e30f;
        l_i[i] = 0.f;
#pragma unroll
        for (int j = 0; j < 4; j++) o[i][j] = 0.f;
    }

    for (int jt = 0; jt <= qi; jt++) {
        const int kbase = jt * 64;
        const float* kptr = qkv + (size_t)kbase * QKV3 + CDIM + h * 64;
        const float* vptr = qkv + (size_t)kbase * QKV3 + 2 * CDIM + h * 64;

        // Load K transposed, V direct
#pragma unroll
        for (int it = 0; it < 4; it++) {
            int slot = tid + it * 256;
            int r  = slot >> 4;
            int d4 = (slot & 15) * 4;
            float4 kv = *reinterpret_cast<const float4*>(&kptr[(size_t)r * QKV3 + d4]);
            Kt[(d4 + 0) * 64 + r] = kv.x;
            Kt[(d4 + 1) * 64 + r] = kv.y;
            Kt[(d4 + 2) * 64 + r] = kv.z;
            Kt[(d4 + 3) * 64 + r] = kv.w;
            float4 vv = *reinterpret_cast<const float4*>(&vptr[(size_t)r * QKV3 + d4]);
            *reinterpret_cast<float4*>(&Vs[r * 64 + d4]) = vv;
        }
        __syncthreads();

        // S = Q K^T (rank-1 over d)
        float s[4][4];
#pragma unroll
        for (int i = 0; i < 4; i++)
#pragma unroll
            for (int j = 0; j < 4; j++) s[i][j] = 0.f;

#pragma unroll 16
        for (int d = 0; d < 64; d++) {
            float4 qa = *reinterpret_cast<const float4*>(&Qt[d * 64 + ty * 4]);
            float4 kb = *reinterpret_cast<const float4*>(&Kt[d * 64 + tx * 4]);
            const float aq[4] = {qa.x, qa.y, qa.z, qa.w};
            const float bk[4] = {kb.x, kb.y, kb.z, kb.w};
#pragma unroll
            for (int i = 0; i < 4; i++)
#pragma unroll
                for (int j = 0; j < 4; j++)
                    s[i][j] = fmaf(aq[i], bk[j], s[i][j]);
        }

        const bool diag = (jt == qi);
#pragma unroll
        for (int i = 0; i < 4; i++) {
#pragma unroll
            for (int j = 0; j < 4; j++) {
                float sv = s[i][j] * SCALE;
                if (diag && (tx * 4 + j) > (ty * 4 + i)) sv = -1e30f;
                s[i][j] = sv;
            }
        }

        // Online softmax per owned row (16-lane butterfly within half-warp)
#pragma unroll
        for (int i = 0; i < 4; i++) {
            float rm = fmaxf(fmaxf(s[i][0], s[i][1]), fmaxf(s[i][2], s[i][3]));
#pragma unroll
            for (int off = 1; off < 16; off <<= 1)
                rm = fmaxf(rm, __shfl_xor_sync(0xffffffffu, rm, off));
            const float mnew  = fmaxf(m_i[i], rm);
            const float alpha = __expf(m_i[i] - mnew);
            float rs = 0.f;
#pragma unroll
            for (int j = 0; j < 4; j++) {
                const float p = __expf(s[i][j] - mnew);
                s[i][j] = p;
                rs += p;
            }
#pragma unroll
            for (int off = 1; off < 16; off <<= 1)
                rs += __shfl_xor_sync(0xffffffffu, rs, off);
            l_i[i] = l_i[i] * alpha + rs;
            m_i[i] = mnew;
#pragma unroll
            for (int j = 0; j < 4; j++) o[i][j] *= alpha;
        }

        // P transposed to smem: Pt[s][r]
#pragma unroll
        for (int i = 0; i < 4; i++)
#pragma unroll
            for (int j = 0; j < 4; j++)
                Pt[(tx * 4 + j) * 65 + ty * 4 + i] = s[i][j];
        __syncthreads();

        // O += P @ V (rank-1 over s)
#pragma unroll 16
        for (int ss = 0; ss < 64; ss++) {
            float4 vv = *reinterpret_cast<const float4*>(&Vs[ss * 64 + tx * 4]);
            const float vb[4] = {vv.x, vv.y, vv.z, vv.w};
            float pr[4];
#pragma unroll
            for (int i = 0; i < 4; i++) pr[i] = Pt[ss * 65 + ty * 4 + i];
#pragma unroll
            for (int i = 0; i < 4; i++)
#pragma unroll
                for (int j = 0; j < 4; j++)
                    o[i][j] = fmaf(pr[i], vb[j], o[i][j]);
        }
        __syncthreads();
    }

    // Normalize and write [n, h*64 + d]
    float* optr = out + (size_t)qbase * CDIM + h * 64;
#pragma unroll
    for (int i = 0; i < 4; i++) {
        const float inv = 1.f / l_i[i];
        float4 v;
        v.x = o[i][0] * inv; v.y = o[i][1] * inv;
        v.z = o[i][2] * inv; v.w = o[i][3] * inv;
        *reinterpret_cast<float4*>(&optr[(size_t)(ty * 4 + i) * CDIM + tx * 4]) = v;
    }
}

// ---------------------------------------------------------------------------
extern "C" void kernel_launch(void* const* d_in, const int* in_sizes, int n_in,
                              void* d_out, int out_size)
{
    // Identify inputs by size (robust to ordering): x=4194304, w_qkv=3145728,
    // w_proj=1048576, b_proj=1024.
    const float* x = nullptr; const float* w_qkv = nullptr;
    const float* w_proj = nullptr; const float* b_proj = nullptr;
    for (int i = 0; i < n_in; i++) {
        switch (in_sizes[i]) {
            case SEQ * CDIM:      x      = (const float*)d_in[i]; break;
            case QKV3 * CDIM:     w_qkv  = (const float*)d_in[i]; break;
            case CDIM * CDIM:     w_proj = (const float*)d_in[i]; break;
            case CDIM:            b_proj = (const float*)d_in[i]; break;
        }
    }
    float* out = (float*)d_out;

    float* qkv = nullptr; float* attn = nullptr;
    cudaGetSymbolAddress((void**)&qkv, g_qkv);
    cudaGetSymbolAddress((void**)&attn, g_attn);

    const int attn_smem = (3 * 4096 + 64 * 65) * (int)sizeof(float);  // 65792 B
    cudaFuncSetAttribute(attn_kernel, cudaFuncAttributeMaxDynamicSharedMemorySize,
                         attn_smem);

    // 1) QKV projection: [4096,1024] @ [3072,1024]^T -> [4096,3072]
    gemm_nt_kernel<false><<<dim3(QKV3 / 128, SEQ / 128), 256>>>(
        x, w_qkv, nullptr, qkv, SEQ, QKV3, CDIM);

    // 2) Causal flash attention -> [4096,1024]
    attn_kernel<<<dim3(SEQ / 64, 16), 256, attn_smem>>>(qkv, attn);

    // 3) Output projection + bias: [4096,1024] @ [1024,1024]^T + b
    gemm_nt_kernel<true><<<dim3(CDIM / 128, SEQ / 128), 256>>>(
        attn, w_proj, b_proj, out, SEQ, CDIM, CDIM);
}

// round 4
// speedup vs baseline: 2.6798x; 2.6798x over previous
#include <cuda_runtime.h>
#include <cuda_bf16.h>

// Problem: B=1, N=4096, H=16, D=64, C=1024
static constexpr int SEQ   = 4096;
static constexpr int CDIM  = 1024;
static constexpr int QKV3  = 3 * CDIM;   // 3072
static constexpr int HEADS = 16;
static constexpr float SCALE = 0.125f;   // 64^-0.5

// ---------------------------------------------------------------------------
// Scratch (device globals; no allocations allowed)
// ---------------------------------------------------------------------------
__device__ float g_qkv [SEQ * QKV3];      // fp32 qkv
__device__ float g_attn[SEQ * CDIM];      // fp32 attention output

__device__ __nv_bfloat16 g_xh[SEQ * CDIM],  g_xl[SEQ * CDIM];
__device__ __nv_bfloat16 g_wqh[QKV3 * CDIM], g_wql[QKV3 * CDIM];
__device__ __nv_bfloat16 g_wph[CDIM * CDIM], g_wpl[CDIM * CDIM];
// per-head contiguous: [h][n][64]
__device__ __nv_bfloat16 g_qh[HEADS * SEQ * 64], g_ql[HEADS * SEQ * 64];
__device__ __nv_bfloat16 g_kh[HEADS * SEQ * 64], g_kl[HEADS * SEQ * 64];
// V transposed: [h][d][n]
__device__ __nv_bfloat16 g_vth[HEADS * 64 * SEQ], g_vtl[HEADS * 64 * SEQ];
__device__ __nv_bfloat16 g_ah[SEQ * CDIM], g_al[SEQ * CDIM];

// ---------------------------------------------------------------------------
// Helpers
// ---------------------------------------------------------------------------
__device__ __forceinline__ void mma16816(float* c, const unsigned* a, const unsigned* b)
{
    asm volatile(
        "mma.sync.aligned.m16n8k16.row.col.f32.bf16.bf16.f32 "
        "{%0,%1,%2,%3}, {%4,%5,%6,%7}, {%8,%9}, {%0,%1,%2,%3};"
        : "+f"(c[0]), "+f"(c[1]), "+f"(c[2]), "+f"(c[3])
        : "r"(a[0]), "r"(a[1]), "r"(a[2]), "r"(a[3]), "r"(b[0]), "r"(b[1]));
}

__device__ __forceinline__ unsigned pack2(float x, float y)
{
    unsigned lo = (unsigned)__bfloat16_as_ushort(__float2bfloat16_rn(x));
    unsigned hi = (unsigned)__bfloat16_as_ushort(__float2bfloat16_rn(y));
    return lo | (hi << 16);
}

__device__ __forceinline__ void split1(float x, unsigned short& h, unsigned short& l)
{
    __nv_bfloat16 hb = __float2bfloat16_rn(x);
    __nv_bfloat16 lb = __float2bfloat16_rn(x - __bfloat162float(hb));
    h = __bfloat16_as_ushort(hb);
    l = __bfloat16_as_ushort(lb);
}

// ---------------------------------------------------------------------------
// Elementwise hi/lo split, 4 floats per thread
// ---------------------------------------------------------------------------
__global__ void split_plain(const float* __restrict__ in,
                            __nv_bfloat16* __restrict__ hi,
                            __nv_bfloat16* __restrict__ lo, int n4)
{
    int i = blockIdx.x * blockDim.x + threadIdx.x;
    if (i >= n4) return;
    float4 v = reinterpret_cast<const float4*>(in)[i];
    unsigned short h0,h1,h2,h3,l0,l1,l2,l3;
    split1(v.x,h0,l0); split1(v.y,h1,l1); split1(v.z,h2,l2); split1(v.w,h3,l3);
    uint2 uh, ul;
    uh.x = (unsigned)h0 | ((unsigned)h1 << 16); uh.y = (unsigned)h2 | ((unsigned)h3 << 16);
    ul.x = (unsigned)l0 | ((unsigned)l1 << 16); ul.y = (unsigned)l2 | ((unsigned)l3 << 16);
    reinterpret_cast<uint2*>(hi)[i] = uh;
    reinterpret_cast<uint2*>(lo)[i] = ul;
}

// qkv fp32 [n][3C] -> Q,K hi/lo per-head [h][n][64]
__global__ void split_qk(const float* __restrict__ qkv,
                         __nv_bfloat16* __restrict__ qh, __nv_bfloat16* __restrict__ ql,
                         __nv_bfloat16* __restrict__ kh, __nv_bfloat16* __restrict__ kl)
{
    int idx = blockIdx.x * 256 + threadIdx.x;      // 16*4096*16 = 1M
    int h  = idx >> 16;
    int r  = idx & 65535;
    int n  = r >> 4;
    int d4 = (r & 15) * 4;
    const float4 q = *reinterpret_cast<const float4*>(&qkv[(size_t)n * QKV3 + h * 64 + d4]);
    const float4 k = *reinterpret_cast<const float4*>(&qkv[(size_t)n * QKV3 + CDIM + h * 64 + d4]);
    size_t o = ((size_t)h << 18) + (size_t)n * 64 + d4;
    unsigned short a0,a1,a2,a3,b0,b1,b2,b3;
    uint2 u;
    split1(q.x,a0,b0); split1(q.y,a1,b1); split1(q.z,a2,b2); split1(q.w,a3,b3);
    u.x = (unsigned)a0 | ((unsigned)a1<<16); u.y = (unsigned)a2 | ((unsigned)a3<<16);
    *reinterpret_cast<uint2*>(&qh[o]) = u;
    u.x = (unsigned)b0 | ((unsigned)b1<<16); u.y = (unsigned)b2 | ((unsigned)b3<<16);
    *reinterpret_cast<uint2*>(&ql[o]) = u;
    split1(k.x,a0,b0); split1(k.y,a1,b1); split1(k.z,a2,b2); split1(k.w,a3,b3);
    u.x = (unsigned)a0 | ((unsigned)a1<<16); u.y = (unsigned)a2 | ((unsigned)a3<<16);
    *reinterpret_cast<uint2*>(&kh[o]) = u;
    u.x = (unsigned)b0 | ((unsigned)b1<<16); u.y = (unsigned)b2 | ((unsigned)b3<<16);
    *reinterpret_cast<uint2*>(&kl[o]) = u;
}

// V: qkv fp32 -> transposed hi/lo [h][d][n]
__global__ void split_v_trans(const float* __restrict__ qkv,
                              __nv_bfloat16* __restrict__ vth,
                              __nv_bfloat16* __restrict__ vtl)
{
    __shared__ float tile[64][65];
    const int h  = blockIdx.y;
    const int nb = blockIdx.x * 64;
    const int tid = threadIdx.x;
#pragma unroll
    for (int it = 0; it < 4; it++) {
        int slot = tid + it * 256;          // 0..1023
        int row  = slot >> 4;               // n within tile
        int d4   = (slot & 15) * 4;
        float4 v = *reinterpret_cast<const float4*>(
            &qkv[(size_t)(nb + row) * QKV3 + 2 * CDIM + h * 64 + d4]);
        tile[row][d4+0] = v.x; tile[row][d4+1] = v.y;
        tile[row][d4+2] = v.z; tile[row][d4+3] = v.w;
    }
    __syncthreads();
    const int d  = tid >> 2;
    const int n0 = (tid & 3) * 16;
    size_t base = ((size_t)h << 18) + (size_t)d * SEQ + nb + n0;
#pragma unroll
    for (int seg = 0; seg < 4; seg++) {
        unsigned short hh[4], ll[4];
#pragma unroll
        for (int j = 0; j < 4; j++) split1(tile[n0 + seg*4 + j][d], hh[j], ll[j]);
        uint2 u;
        u.x = (unsigned)hh[0] | ((unsigned)hh[1]<<16); u.y = (unsigned)hh[2] | ((unsigned)hh[3]<<16);
        *reinterpret_cast<uint2*>(&vth[base + seg*4]) = u;
        u.x = (unsigned)ll[0] | ((unsigned)ll[1]<<16); u.y = (unsigned)ll[2] | ((unsigned)ll[3]<<16);
        *reinterpret_cast<uint2*>(&vtl[base + seg*4]) = u;
    }
}

// ---------------------------------------------------------------------------
// Split-bf16 tensor-core GEMM: C[M,N] = A[M,K] * B[N,K]^T (+bias)
// 128x128 block, 8 warps (2m x 4n), warp 64x32, K-tile 32.
// smem row stride 40 bf16 (80B): bank-conflict-free frag loads + aligned f4.
// ---------------------------------------------------------------------------
template <bool BIAS>
__global__ __launch_bounds__(256, 2) void gemm_nt_mma(
    const __nv_bfloat16* __restrict__ Ah, const __nv_bfloat16* __restrict__ Al,
    const __nv_bfloat16* __restrict__ Bh, const __nv_bfloat16* __restrict__ Bl,
    const float* __restrict__ bias, float* __restrict__ C,
    int M, int N, int K)
{
    __shared__ __nv_bfloat16 sAh[128*40], sAl[128*40], sBh[128*40], sBl[128*40];

    const int bm = blockIdx.y * 128, bn = blockIdx.x * 128;
    const int tid = threadIdx.x;
    const int warp = tid >> 5, lane = tid & 31;
    const int wm = warp >> 2, wn = warp & 3;      // 2 x 4
    const int g = lane >> 2, t = lane & 3;

    float acc[4][4][4];
#pragma unroll
    for (int mi = 0; mi < 4; mi++)
#pragma unroll
        for (int ni = 0; ni < 4; ni++)
#pragma unroll
            for (int r = 0; r < 4; r++) acc[mi][ni][r] = 0.f;

    for (int k0 = 0; k0 < K; k0 += 32) {
#pragma unroll
        for (int it = 0; it < 2; it++) {
            int slot = tid + it * 256;            // 0..511
            int row  = slot >> 2;                 // 0..127
            int kc   = (slot & 3) * 8;            // 0,8,16,24
            size_t ga = (size_t)(bm + row) * K + k0 + kc;
            size_t gb = (size_t)(bn + row) * K + k0 + kc;
            *reinterpret_cast<float4*>(&sAh[row*40 + kc]) = *reinterpret_cast<const float4*>(&Ah[ga]);
            *reinterpret_cast<float4*>(&sAl[row*40 + kc]) = *reinterpret_cast<const float4*>(&Al[ga]);
            *reinterpret_cast<float4*>(&sBh[row*40 + kc]) = *reinterpret_cast<const float4*>(&Bh[gb]);
            *reinterpret_cast<float4*>(&sBl[row*40 + kc]) = *reinterpret_cast<const float4*>(&Bl[gb]);
        }
        __syncthreads();

#pragma unroll
        for (int kk = 0; kk < 32; kk += 16) {
            unsigned bh[4][2], bl[4][2];
#pragma unroll
            for (int ni = 0; ni < 4; ni++) {
                int base = (wn*32 + ni*8 + g) * 40 + kk + 2*t;
                bh[ni][0] = *reinterpret_cast<unsigned*>(&sBh[base]);
                bh[ni][1] = *reinterpret_cast<unsigned*>(&sBh[base + 8]);
                bl[ni][0] = *reinterpret_cast<unsigned*>(&sBl[base]);
                bl[ni][1] = *reinterpret_cast<unsigned*>(&sBl[base + 8]);
            }
#pragma unroll
            for (int mi = 0; mi < 4; mi++) {
                int base = (wm*64 + mi*16 + g) * 40 + kk + 2*t;
                unsigned ah[4], al[4];
                ah[0] = *reinterpret_cast<unsigned*>(&sAh[base]);
                ah[1] = *reinterpret_cast<unsigned*>(&sAh[base + 8*40]);
                ah[2] = *reinterpret_cast<unsigned*>(&sAh[base + 8]);
                ah[3] = *reinterpret_cast<unsigned*>(&sAh[base + 8*40 + 8]);
                al[0] = *reinterpret_cast<unsigned*>(&sAl[base]);
                al[1] = *reinterpret_cast<unsigned*>(&sAl[base + 8*40]);
                al[2] = *reinterpret_cast<unsigned*>(&sAl[base + 8]);
                al[3] = *reinterpret_cast<unsigned*>(&sAl[base + 8*40 + 8]);
#pragma unroll
                for (int ni = 0; ni < 4; ni++) {
                    mma16816(acc[mi][ni], ah, bh[ni]);
                    mma16816(acc[mi][ni], ah, bl[ni]);
                    mma16816(acc[mi][ni], al, bh[ni]);
                }
            }
        }
        __syncthreads();
    }

#pragma unroll
    for (int mi = 0; mi < 4; mi++) {
        int r0 = bm + wm*64 + mi*16 + g;
#pragma unroll
        for (int ni = 0; ni < 4; ni++) {
            int col = bn + wn*32 + ni*8 + 2*t;
            float b0 = 0.f, b1 = 0.f;
            if (BIAS) { b0 = bias[col]; b1 = bias[col + 1]; }
            float2 v0 = {acc[mi][ni][0] + b0, acc[mi][ni][1] + b1};
            float2 v1 = {acc[mi][ni][2] + b0, acc[mi][ni][3] + b1};
            *reinterpret_cast<float2*>(&C[(size_t)r0 * N + col])       = v0;
            *reinterpret_cast<float2*>(&C[(size_t)(r0+8) * N + col])   = v1;
        }
    }
}

// ---------------------------------------------------------------------------
// Flash attention with split-bf16 mma. Block = 128 q-rows x 1 head, 8 warps.
// Each warp owns 16 full rows (8 n-atoms across 64-key tile) -> softmax in
// registers + 4-lane shuffles. P fragments built directly from S accumulators.
// ---------------------------------------------------------------------------
__global__ __launch_bounds__(256, 2) void attn_mma(
    const __nv_bfloat16* __restrict__ Qh, const __nv_bfloat16* __restrict__ Ql,
    const __nv_bfloat16* __restrict__ Kh, const __nv_bfloat16* __restrict__ Kl,
    const __nv_bfloat16* __restrict__ Vth, const __nv_bfloat16* __restrict__ Vtl,
    float* __restrict__ out)
{
    extern __shared__ __nv_bfloat16 sm[];
    __nv_bfloat16* sQh = sm;               // [128][72]
    __nv_bfloat16* sQl = sQh + 128*72;
    __nv_bfloat16* sKh = sQl + 128*72;     // [64 keys][72]
    __nv_bfloat16* sKl = sKh + 64*72;
    __nv_bfloat16* sVh = sKl + 64*72;      // Vt [64 d][72]
    __nv_bfloat16* sVl = sVh + 64*72;

    const int qi = gridDim.x - 1 - blockIdx.x;   // reverse for causal balance
    const int h  = blockIdx.y;
    const int qbase = qi * 128;
    const int tid = threadIdx.x;
    const int warp = tid >> 5, lane = tid & 31;
    const int g = lane >> 2, t = lane & 3;
    const size_t hoff = (size_t)h << 18;         // h * 4096 * 64

    // Load Q tile (hi/lo)
#pragma unroll
    for (int it = 0; it < 4; it++) {
        int slot = tid + it * 256;        // 0..1023
        int row  = slot >> 3;             // 0..127
        int kc   = (slot & 7) * 8;        // 0..56
        size_t gq = hoff + (size_t)(qbase + row) * 64 + kc;
        *reinterpret_cast<float4*>(&sQh[row*72 + kc]) = *reinterpret_cast<const float4*>(&Qh[gq]);
        *reinterpret_cast<float4*>(&sQl[row*72 + kc]) = *reinterpret_cast<const float4*>(&Ql[gq]);
    }

    float o[8][4];
#pragma unroll
    for (int j = 0; j < 8; j++)
#pragma unroll
        for (int r = 0; r < 4; r++) o[j][r] = 0.f;
    float m0 = -1e30f, m1 = -1e30f, l0 = 0.f, l1 = 0.f;

    const int row0 = qbase + warp*16 + g;
    const int row1 = row0 + 8;
    const int jt_max = 2*qi + 1;

    for (int jt = 0; jt <= jt_max; jt++) {
        const int kb = jt * 64;
        // Load K and Vt tiles (hi/lo)
#pragma unroll
        for (int it = 0; it < 2; it++) {
            int slot = tid + it * 256;    // 0..511
            int row  = slot >> 3;         // 0..63
            int kc   = (slot & 7) * 8;
            size_t gk = hoff + (size_t)(kb + row) * 64 + kc;
            size_t gv = hoff + (size_t)row * SEQ + kb + kc;
            *reinterpret_cast<float4*>(&sKh[row*72 + kc]) = *reinterpret_cast<const float4*>(&Kh[gk]);
            *reinterpret_cast<float4*>(&sKl[row*72 + kc]) = *reinterpret_cast<const float4*>(&Kl[gk]);
            *reinterpret_cast<float4*>(&sVh[row*72 + kc]) = *reinterpret_cast<const float4*>(&Vth[gv]);
            *reinterpret_cast<float4*>(&sVl[row*72 + kc]) = *reinterpret_cast<const float4*>(&Vtl[gv]);
        }
        __syncthreads();

        // ---- S = Q K^T ----
        float s[8][4];
#pragma unroll
        for (int j = 0; j < 8; j++)
#pragma unroll
            for (int r = 0; r < 4; r++) s[j][r] = 0.f;

#pragma unroll
        for (int kc = 0; kc < 64; kc += 16) {
            int ab = (warp*16 + g) * 72 + kc + 2*t;
            unsigned qh[4], ql[4];
            qh[0] = *reinterpret_cast<unsigned*>(&sQh[ab]);
            qh[1] = *reinterpret_cast<unsigned*>(&sQh[ab + 8*72]);
            qh[2] = *reinterpret_cast<unsigned*>(&sQh[ab + 8]);
            qh[3] = *reinterpret_cast<unsigned*>(&sQh[ab + 8*72 + 8]);
            ql[0] = *reinterpret_cast<unsigned*>(&sQl[ab]);
            ql[1] = *reinterpret_cast<unsigned*>(&sQl[ab + 8*72]);
            ql[2] = *reinterpret_cast<unsigned*>(&sQl[ab + 8]);
            ql[3] = *reinterpret_cast<unsigned*>(&sQl[ab + 8*72 + 8]);
#pragma unroll
            for (int j = 0; j < 8; j++) {
                int bb = (j*8 + g) * 72 + kc + 2*t;
                unsigned kh[2], kl[2];
                kh[0] = *reinterpret_cast<unsigned*>(&sKh[bb]);
                kh[1] = *reinterpret_cast<unsigned*>(&sKh[bb + 8]);
                kl[0] = *reinterpret_cast<unsigned*>(&sKl[bb]);
                kl[1] = *reinterpret_cast<unsigned*>(&sKl[bb + 8]);
                mma16816(s[j], qh, kh);
                mma16816(s[j], qh, kl);
                mma16816(s[j], ql, kh);
            }
        }

        // ---- scale + causal mask ----
        const bool need_mask = (jt >= 2*qi);
#pragma unroll
        for (int j = 0; j < 8; j++) {
            int c0 = kb + j*8 + 2*t;
            s[j][0] *= SCALE; s[j][1] *= SCALE; s[j][2] *= SCALE; s[j][3] *= SCALE;
            if (need_mask) {
                if (c0     > row0) s[j][0] = -1e30f;
                if (c0 + 1 > row0) s[j][1] = -1e30f;
                if (c0     > row1) s[j][2] = -1e30f;
                if (c0 + 1 > row1) s[j][3] = -1e30f;
            }
        }

        // ---- online softmax (rows row0: c0/c1, row1: c2/c3) ----
        float mx0 = -1e30f, mx1 = -1e30f;
#pragma unroll
        for (int j = 0; j < 8; j++) {
            mx0 = fmaxf(mx0, fmaxf(s[j][0], s[j][1]));
            mx1 = fmaxf(mx1, fmaxf(s[j][2], s[j][3]));
        }
        mx0 = fmaxf(mx0, __shfl_xor_sync(0xffffffffu, mx0, 1));
        mx0 = fmaxf(mx0, __shfl_xor_sync(0xffffffffu, mx0, 2));
        mx1 = fmaxf(mx1, __shfl_xor_sync(0xffffffffu, mx1, 1));
        mx1 = fmaxf(mx1, __shfl_xor_sync(0xffffffffu, mx1, 2));

        const float mn0 = fmaxf(m0, mx0), mn1 = fmaxf(m1, mx1);
        const float a0 = __expf(m0 - mn0), a1 = __expf(m1 - mn1);
        float sum0 = 0.f, sum1 = 0.f;
#pragma unroll
        for (int j = 0; j < 8; j++) {
            s[j][0] = __expf(s[j][0] - mn0); sum0 += s[j][0];
            s[j][1] = __expf(s[j][1] - mn0); sum0 += s[j][1];
            s[j][2] = __expf(s[j][2] - mn1); sum1 += s[j][2];
            s[j][3] = __expf(s[j][3] - mn1); sum1 += s[j][3];
        }
        sum0 += __shfl_xor_sync(0xffffffffu, sum0, 1);
        sum0 += __shfl_xor_sync(0xffffffffu, sum0, 2);
        sum1 += __shfl_xor_sync(0xffffffffu, sum1, 1);
        sum1 += __shfl_xor_sync(0xffffffffu, sum1, 2);
        l0 = l0 * a0 + sum0;  m0 = mn0;
        l1 = l1 * a1 + sum1;  m1 = mn1;
#pragma unroll
        for (int j = 0; j < 8; j++) {
            o[j][0] *= a0; o[j][1] *= a0;
            o[j][2] *= a1; o[j][3] *= a1;
        }

        // ---- O += P V : P frags straight from S registers ----
#pragma unroll
        for (int kc = 0; kc < 4; kc++) {              // 16 keys each
            const int j0 = 2*kc;
            unsigned ph[4], pl[4];
            ph[0] = pack2(s[j0][0],   s[j0][1]);
            ph[1] = pack2(s[j0][2],   s[j0][3]);
            ph[2] = pack2(s[j0+1][0], s[j0+1][1]);
            ph[3] = pack2(s[j0+1][2], s[j0+1][3]);
            {
                float r;
                r = s[j0][0]   - __bfloat162float(__ushort_as_bfloat16((unsigned short)(ph[0] & 0xffff)));
                float r2 = s[j0][1] - __bfloat162float(__ushort_as_bfloat16((unsigned short)(ph[0] >> 16)));
                pl[0] = pack2(r, r2);
                r  = s[j0][2] - __bfloat162float(__ushort_as_bfloat16((unsigned short)(ph[1] & 0xffff)));
                r2 = s[j0][3] - __bfloat162float(__ushort_as_bfloat16((unsigned short)(ph[1] >> 16)));
                pl[1] = pack2(r, r2);
                r  = s[j0+1][0] - __bfloat162float(__ushort_as_bfloat16((unsigned short)(ph[2] & 0xffff)));
                r2 = s[j0+1][1] - __bfloat162float(__ushort_as_bfloat16((unsigned short)(ph[2] >> 16)));
                pl[2] = pack2(r, r2);
                r  = s[j0+1][2] - __bfloat162float(__ushort_as_bfloat16((unsigned short)(ph[3] & 0xffff)));
                r2 = s[j0+1][3] - __bfloat162float(__ushort_as_bfloat16((unsigned short)(ph[3] >> 16)));
                pl[3] = pack2(r, r2);
            }
#pragma unroll
            for (int dj = 0; dj < 8; dj++) {
                int bb = (dj*8 + g) * 72 + kc*16 + 2*t;
                unsigned vh[2], vl[2];
                vh[0] = *reinterpret_cast<unsigned*>(&sVh[bb]);
                vh[1] = *reinterpret_cast<unsigned*>(&sVh[bb + 8]);
                vl[0] = *reinterpret_cast<unsigned*>(&sVl[bb]);
                vl[1] = *reinterpret_cast<unsigned*>(&sVl[bb + 8]);
                mma16816(o[dj], ph, vh);
                mma16816(o[dj], ph, vl);
                mma16816(o[dj], pl, vh);
            }
        }
        __syncthreads();
    }

    // ---- epilogue ----
    const float inv0 = 1.f / l0, inv1 = 1.f / l1;
#pragma unroll
    for (int dj = 0; dj < 8; dj++) {
        int col = h*64 + dj*8 + 2*t;
        float2 v0 = {o[dj][0]*inv0, o[dj][1]*inv0};
        float2 v1 = {o[dj][2]*inv1, o[dj][3]*inv1};
        *reinterpret_cast<float2*>(&out[(size_t)row0 * CDIM + col]) = v0;
        *reinterpret_cast<float2*>(&out[(size_t)row1 * CDIM + col]) = v1;
    }
}

// ---------------------------------------------------------------------------
extern "C" void kernel_launch(void* const* d_in, const int* in_sizes, int n_in,
                              void* d_out, int out_size)
{
    const float* x = nullptr; const float* w_qkv = nullptr;
    const float* w_proj = nullptr; const float* b_proj = nullptr;
    for (int i = 0; i < n_in; i++) {
        switch (in_sizes[i]) {
            case SEQ * CDIM:   x      = (const float*)d_in[i]; break;
            case QKV3 * CDIM:  w_qkv  = (const float*)d_in[i]; break;
            case CDIM * CDIM:  w_proj = (const float*)d_in[i]; break;
            case CDIM:         b_proj = (const float*)d_in[i]; break;
        }
    }
    float* out = (float*)d_out;

    float *qkv, *attn;
    __nv_bfloat16 *xh,*xl,*wqh,*wql,*wph,*wpl,*qh,*ql,*kh,*kl,*vth,*vtl,*ah,*al;
    cudaGetSymbolAddress((void**)&qkv, g_qkv);
    cudaGetSymbolAddress((void**)&attn, g_attn);
    cudaGetSymbolAddress((void**)&xh, g_xh);   cudaGetSymbolAddress((void**)&xl, g_xl);
    cudaGetSymbolAddress((void**)&wqh, g_wqh); cudaGetSymbolAddress((void**)&wql, g_wql);
    cudaGetSymbolAddress((void**)&wph, g_wph); cudaGetSymbolAddress((void**)&wpl, g_wpl);
    cudaGetSymbolAddress((void**)&qh, g_qh);   cudaGetSymbolAddress((void**)&ql, g_ql);
    cudaGetSymbolAddress((void**)&kh, g_kh);   cudaGetSymbolAddress((void**)&kl, g_kl);
    cudaGetSymbolAddress((void**)&vth, g_vth); cudaGetSymbolAddress((void**)&vtl, g_vtl);
    cudaGetSymbolAddress((void**)&ah, g_ah);   cudaGetSymbolAddress((void**)&al, g_al);

    const int attn_smem = (2*128*72 + 4*64*72) * (int)sizeof(__nv_bfloat16);  // 73728
    cudaFuncSetAttribute(attn_mma, cudaFuncAttributeMaxDynamicSharedMemorySize, attn_smem);

    // split inputs and weights
    split_plain<<<(SEQ*CDIM/4 + 255)/256, 256>>>(x, xh, xl, SEQ*CDIM/4);
    split_plain<<<(QKV3*CDIM/4 + 255)/256, 256>>>(w_qkv, wqh, wql, QKV3*CDIM/4);
    split_plain<<<(CDIM*CDIM/4 + 255)/256, 256>>>(w_proj, wph, wpl, CDIM*CDIM/4);

    // 1) QKV projection
    gemm_nt_mma<false><<<dim3(QKV3/128, SEQ/128), 256>>>(
        xh, xl, wqh, wql, nullptr, qkv, SEQ, QKV3, CDIM);

    // 2) head-layout splits
    split_qk<<<HEADS*SEQ*16/256, 256>>>(qkv, qh, ql, kh, kl);
    split_v_trans<<<dim3(SEQ/64, HEADS), 256>>>(qkv, vth, vtl);

    // 3) attention
    attn_mma<<<dim3(SEQ/128, HEADS), 256, attn_smem>>>(qh, ql, kh, kl, vth, vtl, attn);

    // 4) output projection
    split_plain<<<(SEQ*CDIM/4 + 255)/256, 256>>>(attn, ah, al, SEQ*CDIM/4);
    gemm_nt_mma<true><<<dim3(CDIM/128, SEQ/128), 256>>>(
        ah, al, wph, wpl, b_proj, out, SEQ, CDIM, CDIM);
}

// round 8
// speedup vs baseline: 2.9191x; 1.0893x over previous
#include <cuda_runtime.h>
#include <cuda_bf16.h>

// Problem: B=1, N=4096, H=16, D=64, C=1024
static constexpr int SEQ   = 4096;
static constexpr int CDIM  = 1024;
static constexpr int QKV3  = 3 * CDIM;   // 3072
static constexpr int HEADS = 16;
static constexpr float SCALE = 0.125f;   // 64^-0.5

// ---------------------------------------------------------------------------
// Scratch (device globals; no allocations allowed)
// ---------------------------------------------------------------------------
__device__ float g_qkv [SEQ * QKV3];      // fp32 qkv

__device__ __nv_bfloat16 g_xh[SEQ * CDIM],  g_xl[SEQ * CDIM];
__device__ __nv_bfloat16 g_wqh[QKV3 * CDIM], g_wql[QKV3 * CDIM];
__device__ __nv_bfloat16 g_wph[CDIM * CDIM], g_wpl[CDIM * CDIM];
// per-head contiguous: [h][n][64]
__device__ __nv_bfloat16 g_qh[HEADS * SEQ * 64], g_ql[HEADS * SEQ * 64];
__device__ __nv_bfloat16 g_kh[HEADS * SEQ * 64], g_kl[HEADS * SEQ * 64];
// V transposed: [h][d][n]
__device__ __nv_bfloat16 g_vth[HEADS * 64 * SEQ], g_vtl[HEADS * 64 * SEQ];
// attention output split (written directly by attn epilogue)
__device__ __nv_bfloat16 g_ah[SEQ * CDIM], g_al[SEQ * CDIM];

// ---------------------------------------------------------------------------
// Helpers
// ---------------------------------------------------------------------------
__device__ __forceinline__ void mma16816(float* c, const unsigned* a, const unsigned* b)
{
    asm volatile(
        "mma.sync.aligned.m16n8k16.row.col.f32.bf16.bf16.f32 "
        "{%0,%1,%2,%3}, {%4,%5,%6,%7}, {%8,%9}, {%0,%1,%2,%3};"
        : "+f"(c[0]), "+f"(c[1]), "+f"(c[2]), "+f"(c[3])
        : "r"(a[0]), "r"(a[1]), "r"(a[2]), "r"(a[3]), "r"(b[0]), "r"(b[1]));
}

__device__ __forceinline__ unsigned pack2(float x, float y)
{
    unsigned lo = (unsigned)__bfloat16_as_ushort(__float2bfloat16_rn(x));
    unsigned hi = (unsigned)__bfloat16_as_ushort(__float2bfloat16_rn(y));
    return lo | (hi << 16);
}

__device__ __forceinline__ void split1(float x, unsigned short& h, unsigned short& l)
{
    __nv_bfloat16 hb = __float2bfloat16_rn(x);
    __nv_bfloat16 lb = __float2bfloat16_rn(x - __bfloat162float(hb));
    h = __bfloat16_as_ushort(hb);
    l = __bfloat16_as_ushort(lb);
}

__device__ __forceinline__ void cp16(void* s, const void* g)
{
    unsigned sa = (unsigned)__cvta_generic_to_shared(s);
    asm volatile("cp.async.cg.shared.global [%0], [%1], 16;" :: "r"(sa), "l"(g));
}
__device__ __forceinline__ void cp_commit()
{
    asm volatile("cp.async.commit_group;");
}
__device__ __forceinline__ void cp_wait_all()
{
    asm volatile("cp.async.wait_group 0;");
}

// ---------------------------------------------------------------------------
// Elementwise hi/lo split, 4 floats per thread
// ---------------------------------------------------------------------------
__global__ void split_plain(const float* __restrict__ in,
                            __nv_bfloat16* __restrict__ hi,
                            __nv_bfloat16* __restrict__ lo, int n4)
{
    int i = blockIdx.x * blockDim.x + threadIdx.x;
    if (i >= n4) return;
    float4 v = reinterpret_cast<const float4*>(in)[i];
    unsigned short h0,h1,h2,h3,l0,l1,l2,l3;
    split1(v.x,h0,l0); split1(v.y,h1,l1); split1(v.z,h2,l2); split1(v.w,h3,l3);
    uint2 uh, ul;
    uh.x = (unsigned)h0 | ((unsigned)h1 << 16); uh.y = (unsigned)h2 | ((unsigned)h3 << 16);
    ul.x = (unsigned)l0 | ((unsigned)l1 << 16); ul.y = (unsigned)l2 | ((unsigned)l3 << 16);
    reinterpret_cast<uint2*>(hi)[i] = uh;
    reinterpret_cast<uint2*>(lo)[i] = ul;
}

// qkv fp32 [n][3C] -> Q,K hi/lo per-head [h][n][64]
__global__ void split_qk(const float* __restrict__ qkv,
                         __nv_bfloat16* __restrict__ qh, __nv_bfloat16* __restrict__ ql,
                         __nv_bfloat16* __restrict__ kh, __nv_bfloat16* __restrict__ kl)
{
    int idx = blockIdx.x * 256 + threadIdx.x;      // 16*4096*16 = 1M
    int h  = idx >> 16;
    int r  = idx & 65535;
    int n  = r >> 4;
    int d4 = (r & 15) * 4;
    const float4 q = *reinterpret_cast<const float4*>(&qkv[(size_t)n * QKV3 + h * 64 + d4]);
    const float4 k = *reinterpret_cast<const float4*>(&qkv[(size_t)n * QKV3 + CDIM + h * 64 + d4]);
    size_t o = ((size_t)h << 18) + (size_t)n * 64 + d4;
    unsigned short a0,a1,a2,a3,b0,b1,b2,b3;
    uint2 u;
    split1(q.x,a0,b0); split1(q.y,a1,b1); split1(q.z,a2,b2); split1(q.w,a3,b3);
    u.x = (unsigned)a0 | ((unsigned)a1<<16); u.y = (unsigned)a2 | ((unsigned)a3<<16);
    *reinterpret_cast<uint2*>(&qh[o]) = u;
    u.x = (unsigned)b0 | ((unsigned)b1<<16); u.y = (unsigned)b2 | ((unsigned)b3<<16);
    *reinterpret_cast<uint2*>(&ql[o]) = u;
    split1(k.x,a0,b0); split1(k.y,a1,b1); split1(k.z,a2,b2); split1(k.w,a3,b3);
    u.x = (unsigned)a0 | ((unsigned)a1<<16); u.y = (unsigned)a2 | ((unsigned)a3<<16);
    *reinterpret_cast<uint2*>(&kh[o]) = u;
    u.x = (unsigned)b0 | ((unsigned)b1<<16); u.y = (unsigned)b2 | ((unsigned)b3<<16);
    *reinterpret_cast<uint2*>(&kl[o]) = u;
}

// V: qkv fp32 -> transposed hi/lo [h][d][n]
__global__ void split_v_trans(const float* __restrict__ qkv,
                              __nv_bfloat16* __restrict__ vth,
                              __nv_bfloat16* __restrict__ vtl)
{
    __shared__ float tile[64][65];
    const int h  = blockIdx.y;
    const int nb = blockIdx.x * 64;
    const int tid = threadIdx.x;
#pragma unroll
    for (int it = 0; it < 4; it++) {
        int slot = tid + it * 256;          // 0..1023
        int row  = slot >> 4;               // n within tile
        int d4   = (slot & 15) * 4;
        float4 v = *reinterpret_cast<const float4*>(
            &qkv[(size_t)(nb + row) * QKV3 + 2 * CDIM + h * 64 + d4]);
        tile[row][d4+0] = v.x; tile[row][d4+1] = v.y;
        tile[row][d4+2] = v.z; tile[row][d4+3] = v.w;
    }
    __syncthreads();
    const int d  = tid >> 2;
    const int n0 = (tid & 3) * 16;
    size_t base = ((size_t)h << 18) + (size_t)d * SEQ + nb + n0;
#pragma unroll
    for (int seg = 0; seg < 4; seg++) {
        unsigned short hh[4], ll[4];
#pragma unroll
        for (int j = 0; j < 4; j++) split1(tile[n0 + seg*4 + j][d], hh[j], ll[j]);
        uint2 u;
        u.x = (unsigned)hh[0] | ((unsigned)hh[1]<<16); u.y = (unsigned)hh[2] | ((unsigned)hh[3]<<16);
        *reinterpret_cast<uint2*>(&vth[base + seg*4]) = u;
        u.x = (unsigned)ll[0] | ((unsigned)ll[1]<<16); u.y = (unsigned)ll[2] | ((unsigned)ll[3]<<16);
        *reinterpret_cast<uint2*>(&vtl[base + seg*4]) = u;
    }
}

// ---------------------------------------------------------------------------
// Split-bf16 tensor-core GEMM with 2-stage cp.async pipeline.
// C[M,N] = A[M,K] * B[N,K]^T (+bias). 128x128 block, 8 warps (2m x 4n),
// warp 64x32, K-tile 32, smem row stride 40 bf16.
// ---------------------------------------------------------------------------
static constexpr int G_STG = 4 * 128 * 40;   // bf16 per stage (20480)

template <bool BIAS>
__global__ __launch_bounds__(256, 2) void gemm_nt_mma(
    const __nv_bfloat16* __restrict__ Ah, const __nv_bfloat16* __restrict__ Al,
    const __nv_bfloat16* __restrict__ Bh, const __nv_bfloat16* __restrict__ Bl,
    const float* __restrict__ bias, float* __restrict__ C,
    int M, int N, int K)
{
    extern __shared__ __nv_bfloat16 smem[];

    const int bm = blockIdx.y * 128, bn = blockIdx.x * 128;
    const int tid = threadIdx.x;
    const int warp = tid >> 5, lane = tid & 31;
    const int wm = warp >> 2, wn = warp & 3;      // 2 x 4
    const int g = lane >> 2, t = lane & 3;

    float acc[4][4][4];
#pragma unroll
    for (int mi = 0; mi < 4; mi++)
#pragma unroll
        for (int ni = 0; ni < 4; ni++)
#pragma unroll
            for (int r = 0; r < 4; r++) acc[mi][ni][r] = 0.f;

    auto load_tile = [&](int st, int k0) {
        __nv_bfloat16* sAh = smem + st * G_STG;
        __nv_bfloat16* sAl = sAh + 128*40;
        __nv_bfloat16* sBh = sAh + 2*128*40;
        __nv_bfloat16* sBl = sAh + 3*128*40;
#pragma unroll
        for (int it = 0; it < 2; it++) {
            int slot = tid + it * 256;            // 0..511
            int row  = slot >> 2;                 // 0..127
            int kc   = (slot & 3) * 8;            // 0,8,16,24
            size_t ga = (size_t)(bm + row) * K + k0 + kc;
            size_t gb = (size_t)(bn + row) * K + k0 + kc;
            cp16(&sAh[row*40 + kc], &Ah[ga]);
            cp16(&sAl[row*40 + kc], &Al[ga]);
            cp16(&sBh[row*40 + kc], &Bh[gb]);
            cp16(&sBl[row*40 + kc], &Bl[gb]);
        }
        cp_commit();
    };

    load_tile(0, 0);
    int stage = 0;

    for (int k0 = 0; k0 < K; k0 += 32) {
        cp_wait_all();
        __syncthreads();
        if (k0 + 32 < K) load_tile(stage ^ 1, k0 + 32);

        const __nv_bfloat16* sAh = smem + stage * G_STG;
        const __nv_bfloat16* sAl = sAh + 128*40;
        const __nv_bfloat16* sBh = sAh + 2*128*40;
        const __nv_bfloat16* sBl = sAh + 3*128*40;

#pragma unroll
        for (int kk = 0; kk < 32; kk += 16) {
            unsigned bh[4][2], bl[4][2];
#pragma unroll
            for (int ni = 0; ni < 4; ni++) {
                int base = (wn*32 + ni*8 + g) * 40 + kk + 2*t;
                bh[ni][0] = *reinterpret_cast<const unsigned*>(&sBh[base]);
                bh[ni][1] = *reinterpret_cast<const unsigned*>(&sBh[base + 8]);
                bl[ni][0] = *reinterpret_cast<const unsigned*>(&sBl[base]);
                bl[ni][1] = *reinterpret_cast<const unsigned*>(&sBl[base + 8]);
            }
#pragma unroll
            for (int mi = 0; mi < 4; mi++) {
                int base = (wm*64 + mi*16 + g) * 40 + kk + 2*t;
                unsigned ah[4], al[4];
                ah[0] = *reinterpret_cast<const unsigned*>(&sAh[base]);
                ah[1] = *reinterpret_cast<const unsigned*>(&sAh[base + 8*40]);
                ah[2] = *reinterpret_cast<const unsigned*>(&sAh[base + 8]);
                ah[3] = *reinterpret_cast<const unsigned*>(&sAh[base + 8*40 + 8]);
                al[0] = *reinterpret_cast<const unsigned*>(&sAl[base]);
                al[1] = *reinterpret_cast<const unsigned*>(&sAl[base + 8*40]);
                al[2] = *reinterpret_cast<const unsigned*>(&sAl[base + 8]);
                al[3] = *reinterpret_cast<const unsigned*>(&sAl[base + 8*40 + 8]);
#pragma unroll
                for (int ni = 0; ni < 4; ni++) {
                    mma16816(acc[mi][ni], ah, bh[ni]);
                    mma16816(acc[mi][ni], ah, bl[ni]);
                    mma16816(acc[mi][ni], al, bh[ni]);
                }
            }
        }
        stage ^= 1;
    }

#pragma unroll
    for (int mi = 0; mi < 4; mi++) {
        int r0 = bm + wm*64 + mi*16 + g;
#pragma unroll
        for (int ni = 0; ni < 4; ni++) {
            int col = bn + wn*32 + ni*8 + 2*t;
            float b0 = 0.f, b1 = 0.f;
            if (BIAS) { b0 = bias[col]; b1 = bias[col + 1]; }
            float2 v0 = {acc[mi][ni][0] + b0, acc[mi][ni][1] + b1};
            float2 v1 = {acc[mi][ni][2] + b0, acc[mi][ni][3] + b1};
            *reinterpret_cast<float2*>(&C[(size_t)r0 * N + col])       = v0;
            *reinterpret_cast<float2*>(&C[(size_t)(r0+8) * N + col])   = v1;
        }
    }
}

// ---------------------------------------------------------------------------
// Flash attention, split-bf16 mma, 2-stage cp.async pipeline on K/V tiles.
// Block = 128 q-rows x 1 head, 8 warps, each warp owns 16 full rows.
// Epilogue writes hi/lo bf16 directly (fused split for the proj GEMM).
// ---------------------------------------------------------------------------
static constexpr int A_Q   = 2 * 128 * 72;   // Q hi+lo bf16 (18432)
static constexpr int A_STG = 4 * 64 * 72;    // K/V hi+lo per stage (18432)

__global__ __launch_bounds__(256, 2) void attn_mma(
    const __nv_bfloat16* __restrict__ Qh, const __nv_bfloat16* __restrict__ Ql,
    const __nv_bfloat16* __restrict__ Kh, const __nv_bfloat16* __restrict__ Kl,
    const __nv_bfloat16* __restrict__ Vth, const __nv_bfloat16* __restrict__ Vtl,
    __nv_bfloat16* __restrict__ outh, __nv_bfloat16* __restrict__ outl)
{
    extern __shared__ __nv_bfloat16 sm[];
    __nv_bfloat16* sQh = sm;               // [128][72]
    __nv_bfloat16* sQl = sm + 128*72;
    __nv_bfloat16* kvb = sm + A_Q;

    const int qi = gridDim.x - 1 - blockIdx.x;   // reverse for causal balance
    const int h  = blockIdx.y;
    const int qbase = qi * 128;
    const int tid = threadIdx.x;
    const int warp = tid >> 5, lane = tid & 31;
    const int g = lane >> 2, t = lane & 3;
    const size_t hoff = (size_t)h << 18;         // h * 4096 * 64

    auto load_kv = [&](int st, int jt) {
        __nv_bfloat16* sKh = kvb + st * A_STG;
        __nv_bfloat16* sKl = sKh + 64*72;
        __nv_bfloat16* sVh = sKh + 2*64*72;
        __nv_bfloat16* sVl = sKh + 3*64*72;
        const int kb = jt * 64;
#pragma unroll
        for (int it = 0; it < 2; it++) {
            int slot = tid + it * 256;    // 0..511
            int row  = slot >> 3;         // 0..63
            int kc   = (slot & 7) * 8;
            size_t gk = hoff + (size_t)(kb + row) * 64 + kc;
            size_t gv = hoff + (size_t)row * SEQ + kb + kc;
            cp16(&sKh[row*72 + kc], &Kh[gk]);
            cp16(&sKl[row*72 + kc], &Kl[gk]);
            cp16(&sVh[row*72 + kc], &Vth[gv]);
            cp16(&sVl[row*72 + kc], &Vtl[gv]);
        }
        cp_commit();
    };

    // Q tile (hi/lo) via cp.async as well
#pragma unroll
    for (int it = 0; it < 4; it++) {
        int slot = tid + it * 256;        // 0..1023
        int row  = slot >> 3;             // 0..127
        int kc   = (slot & 7) * 8;        // 0..56
        size_t gq = hoff + (size_t)(qbase + row) * 64 + kc;
        cp16(&sQh[row*72 + kc], &Qh[gq]);
        cp16(&sQl[row*72 + kc], &Ql[gq]);
    }
    cp_commit();
    load_kv(0, 0);
    int stage = 0;

    float o[8][4];
#pragma unroll
    for (int j = 0; j < 8; j++)
#pragma unroll
        for (int r = 0; r < 4; r++) o[j][r] = 0.f;
    float m0 = -1e30f, m1 = -1e30f, l0 = 0.f, l1 = 0.f;

    const int row0 = qbase + warp*16 + g;
    const int row1 = row0 + 8;
    const int jt_max = 2*qi + 1;

    for (int jt = 0; jt <= jt_max; jt++) {
        cp_wait_all();
        __syncthreads();
        if (jt < jt_max) load_kv(stage ^ 1, jt + 1);

        const __nv_bfloat16* sKh = kvb + stage * A_STG;
        const __nv_bfloat16* sKl = sKh + 64*72;
        const __nv_bfloat16* sVh = sKh + 2*64*72;
        const __nv_bfloat16* sVl = sKh + 3*64*72;
        const int kb = jt * 64;

        // ---- S = Q K^T ----
        float s[8][4];
#pragma unroll
        for (int j = 0; j < 8; j++)
#pragma unroll
            for (int r = 0; r < 4; r++) s[j][r] = 0.f;

#pragma unroll
        for (int kc = 0; kc < 64; kc += 16) {
            int ab = (warp*16 + g) * 72 + kc + 2*t;
            unsigned qh[4], ql[4];
            qh[0] = *reinterpret_cast<const unsigned*>(&sQh[ab]);
            qh[1] = *reinterpret_cast<const unsigned*>(&sQh[ab + 8*72]);
            qh[2] = *reinterpret_cast<const unsigned*>(&sQh[ab + 8]);
            qh[3] = *reinterpret_cast<const unsigned*>(&sQh[ab + 8*72 + 8]);
            ql[0] = *reinterpret_cast<const unsigned*>(&sQl[ab]);
            ql[1] = *reinterpret_cast<const unsigned*>(&sQl[ab + 8*72]);
            ql[2] = *reinterpret_cast<const unsigned*>(&sQl[ab + 8]);
            ql[3] = *reinterpret_cast<const unsigned*>(&sQl[ab + 8*72 + 8]);
#pragma unroll
            for (int j = 0; j < 8; j++) {
                int bb = (j*8 + g) * 72 + kc + 2*t;
                unsigned kh[2], kl[2];
                kh[0] = *reinterpret_cast<const unsigned*>(&sKh[bb]);
                kh[1] = *reinterpret_cast<const unsigned*>(&sKh[bb + 8]);
                kl[0] = *reinterpret_cast<const unsigned*>(&sKl[bb]);
                kl[1] = *reinterpret_cast<const unsigned*>(&sKl[bb + 8]);
                mma16816(s[j], qh, kh);
                mma16816(s[j], qh, kl);
                mma16816(s[j], ql, kh);
            }
        }

        // ---- scale + causal mask ----
        const bool need_mask = (jt >= 2*qi);
#pragma unroll
        for (int j = 0; j < 8; j++) {
            int c0 = kb + j*8 + 2*t;
            s[j][0] *= SCALE; s[j][1] *= SCALE; s[j][2] *= SCALE; s[j][3] *= SCALE;
            if (need_mask) {
                if (c0     > row0) s[j][0] = -1e30f;
                if (c0 + 1 > row0) s[j][1] = -1e30f;
                if (c0     > row1) s[j][2] = -1e30f;
                if (c0 + 1 > row1) s[j][3] = -1e30f;
            }
        }

        // ---- online softmax ----
        float mx0 = -1e30f, mx1 = -1e30f;
#pragma unroll
        for (int j = 0; j < 8; j++) {
            mx0 = fmaxf(mx0, fmaxf(s[j][0], s[j][1]));
            mx1 = fmaxf(mx1, fmaxf(s[j][2], s[j][3]));
        }
        mx0 = fmaxf(mx0, __shfl_xor_sync(0xffffffffu, mx0, 1));
        mx0 = fmaxf(mx0, __shfl_xor_sync(0xffffffffu, mx0, 2));
        mx1 = fmaxf(mx1, __shfl_xor_sync(0xffffffffu, mx1, 1));
        mx1 = fmaxf(mx1, __shfl_xor_sync(0xffffffffu, mx1, 2));

        const float mn0 = fmaxf(m0, mx0), mn1 = fmaxf(m1, mx1);
        const float a0 = __expf(m0 - mn0), a1 = __expf(m1 - mn1);
        float sum0 = 0.f, sum1 = 0.f;
#pragma unroll
        for (int j = 0; j < 8; j++) {
            s[j][0] = __expf(s[j][0] - mn0); sum0 += s[j][0];
            s[j][1] = __expf(s[j][1] - mn0); sum0 += s[j][1];
            s[j][2] = __expf(s[j][2] - mn1); sum1 += s[j][2];
            s[j][3] = __expf(s[j][3] - mn1); sum1 += s[j][3];
        }
        sum0 += __shfl_xor_sync(0xffffffffu, sum0, 1);
        sum0 += __shfl_xor_sync(0xffffffffu, sum0, 2);
        sum1 += __shfl_xor_sync(0xffffffffu, sum1, 1);
        sum1 += __shfl_xor_sync(0xffffffffu, sum1, 2);
        l0 = l0 * a0 + sum0;  m0 = mn0;
        l1 = l1 * a1 + sum1;  m1 = mn1;
#pragma unroll
        for (int j = 0; j < 8; j++) {
            o[j][0] *= a0; o[j][1] *= a0;
            o[j][2] *= a1; o[j][3] *= a1;
        }

        // ---- O += P V : P frags straight from S registers ----
#pragma unroll
        for (int kc = 0; kc < 4; kc++) {              // 16 keys each
            const int j0 = 2*kc;
            unsigned ph[4], pl[4];
            ph[0] = pack2(s[j0][0],   s[j0][1]);
            ph[1] = pack2(s[j0][2],   s[j0][3]);
            ph[2] = pack2(s[j0+1][0], s[j0+1][1]);
            ph[3] = pack2(s[j0+1][2], s[j0+1][3]);
            {
                float r, r2;
                r  = s[j0][0] - __bfloat162float(__ushort_as_bfloat16((unsigned short)(ph[0] & 0xffff)));
                r2 = s[j0][1] - __bfloat162float(__ushort_as_bfloat16((unsigned short)(ph[0] >> 16)));
                pl[0] = pack2(r, r2);
                r  = s[j0][2] - __bfloat162float(__ushort_as_bfloat16((unsigned short)(ph[1] & 0xffff)));
                r2 = s[j0][3] - __bfloat162float(__ushort_as_bfloat16((unsigned short)(ph[1] >> 16)));
                pl[1] = pack2(r, r2);
                r  = s[j0+1][0] - __bfloat162float(__ushort_as_bfloat16((unsigned short)(ph[2] & 0xffff)));
                r2 = s[j0+1][1] - __bfloat162float(__ushort_as_bfloat16((unsigned short)(ph[2] >> 16)));
                pl[2] = pack2(r, r2);
                r  = s[j0+1][2] - __bfloat162float(__ushort_as_bfloat16((unsigned short)(ph[3] & 0xffff)));
                r2 = s[j0+1][3] - __bfloat162float(__ushort_as_bfloat16((unsigned short)(ph[3] >> 16)));
                pl[3] = pack2(r, r2);
            }
#pragma unroll
            for (int dj = 0; dj < 8; dj++) {
                int bb = (dj*8 + g) * 72 + kc*16 + 2*t;
                unsigned vh[2], vl[2];
                vh[0] = *reinterpret_cast<const unsigned*>(&sVh[bb]);
                vh[1] = *reinterpret_cast<const unsigned*>(&sVh[bb + 8]);
                vl[0] = *reinterpret_cast<const unsigned*>(&sVl[bb]);
                vl[1] = *reinterpret_cast<const unsigned*>(&sVl[bb + 8]);
                mma16816(o[dj], ph, vh);
                mma16816(o[dj], ph, vl);
                mma16816(o[dj], pl, vh);
            }
        }
        stage ^= 1;
    }

    // ---- epilogue: normalize + split hi/lo directly ----
    const float inv0 = 1.f / l0, inv1 = 1.f / l1;
#pragma unroll
    for (int dj = 0; dj < 8; dj++) {
        int col = h*64 + dj*8 + 2*t;
        float v00 = o[dj][0]*inv0, v01 = o[dj][1]*inv0;
        float v10 = o[dj][2]*inv1, v11 = o[dj][3]*inv1;
        unsigned short h0,h1,l0s,l1s;
        split1(v00, h0, l0s); split1(v01, h1, l1s);
        *reinterpret_cast<unsigned*>(&outh[(size_t)row0 * CDIM + col]) =
            (unsigned)h0 | ((unsigned)h1 << 16);
        *reinterpret_cast<unsigned*>(&outl[(size_t)row0 * CDIM + col]) =
            (unsigned)l0s | ((unsigned)l1s << 16);
        split1(v10, h0, l0s); split1(v11, h1, l1s);
        *reinterpret_cast<unsigned*>(&outh[(size_t)row1 * CDIM + col]) =
            (unsigned)h0 | ((unsigned)h1 << 16);
        *reinterpret_cast<unsigned*>(&outl[(size_t)row1 * CDIM + col]) =
            (unsigned)l0s | ((unsigned)l1s << 16);
    }
}

// ---------------------------------------------------------------------------
extern "C" void kernel_launch(void* const* d_in, const int* in_sizes, int n_in,
                              void* d_out, int out_size)
{
    const float* x = nullptr; const float* w_qkv = nullptr;
    const float* w_proj = nullptr; const float* b_proj = nullptr;
    for (int i = 0; i < n_in; i++) {
        switch (in_sizes[i]) {
            case SEQ * CDIM:   x      = (const float*)d_in[i]; break;
            case QKV3 * CDIM:  w_qkv  = (const float*)d_in[i]; break;
            case CDIM * CDIM:  w_proj = (const float*)d_in[i]; break;
            case CDIM:         b_proj = (const float*)d_in[i]; break;
        }
    }
    float* out = (float*)d_out;

    float *qkv;
    __nv_bfloat16 *xh,*xl,*wqh,*wql,*wph,*wpl,*qh,*ql,*kh,*kl,*vth,*vtl,*ah,*al;
    cudaGetSymbolAddress((void**)&qkv, g_qkv);
    cudaGetSymbolAddress((void**)&xh, g_xh);   cudaGetSymbolAddress((void**)&xl, g_xl);
    cudaGetSymbolAddress((void**)&wqh, g_wqh); cudaGetSymbolAddress((void**)&wql, g_wql);
    cudaGetSymbolAddress((void**)&wph, g_wph); cudaGetSymbolAddress((void**)&wpl, g_wpl);
    cudaGetSymbolAddress((void**)&qh, g_qh);   cudaGetSymbolAddress((void**)&ql, g_ql);
    cudaGetSymbolAddress((void**)&kh, g_kh);   cudaGetSymbolAddress((void**)&kl, g_kl);
    cudaGetSymbolAddress((void**)&vth, g_vth); cudaGetSymbolAddress((void**)&vtl, g_vtl);
    cudaGetSymbolAddress((void**)&ah, g_ah);   cudaGetSymbolAddress((void**)&al, g_al);

    const int gemm_smem = 2 * G_STG * (int)sizeof(__nv_bfloat16);          // 81920
    const int attn_smem = (A_Q + 2 * A_STG) * (int)sizeof(__nv_bfloat16);  // 110592
    cudaFuncSetAttribute(gemm_nt_mma<false>, cudaFuncAttributeMaxDynamicSharedMemorySize, gemm_smem);
    cudaFuncSetAttribute(gemm_nt_mma<true>,  cudaFuncAttributeMaxDynamicSharedMemorySize, gemm_smem);
    cudaFuncSetAttribute(attn_mma, cudaFuncAttributeMaxDynamicSharedMemorySize, attn_smem);

    // split inputs and weights
    split_plain<<<(SEQ*CDIM/4 + 255)/256, 256>>>(x, xh, xl, SEQ*CDIM/4);
    split_plain<<<(QKV3*CDIM/4 + 255)/256, 256>>>(w_qkv, wqh, wql, QKV3*CDIM/4);
    split_plain<<<(CDIM*CDIM/4 + 255)/256, 256>>>(w_proj, wph, wpl, CDIM*CDIM/4);

    // 1) QKV projection
    gemm_nt_mma<false><<<dim3(QKV3/128, SEQ/128), 256, gemm_smem>>>(
        xh, xl, wqh, wql, nullptr, qkv, SEQ, QKV3, CDIM);

    // 2) head-layout splits
    split_qk<<<HEADS*SEQ*16/256, 256>>>(qkv, qh, ql, kh, kl);
    split_v_trans<<<dim3(SEQ/64, HEADS), 256>>>(qkv, vth, vtl);

    // 3) attention (writes hi/lo directly)
    attn_mma<<<dim3(SEQ/128, HEADS), 256, attn_smem>>>(
        qh, ql, kh, kl, vth, vtl, ah, al);

    // 4) output projection
    gemm_nt_mma<true><<<dim3(CDIM/128, SEQ/128), 256, gemm_smem>>>(
        ah, al, wph, wpl, b_proj, out, SEQ, CDIM, CDIM);
}